// round 3
// baseline (speedup 1.0000x reference)
#include <cuda_runtime.h>
#include <cstdint>
#include <cstddef>

// Wigner D matrices per quaternion: D1 = 3x3 (l=1), D2 = 5x5 (l=2).
__device__ float g_D1[16 * 9];
__device__ float g_D2[16 * 25];

// Build z-rotation matrix of size d=2l+1.
// Reference order: sin on anti-diagonal first, then cos on diagonal (center -> cos).
__device__ void zrot(float ang, int d, float* M) {
    int l = (d - 1) / 2;
    for (int x = 0; x < d * d; x++) M[x] = 0.0f;
    for (int idx = 0; idx < d; idx++) {
        float fr = (float)(l - idx);
        M[idx * d + (d - 1 - idx)] = sinf(fr * ang);
        M[idx * d + idx]           = cosf(fr * ang);
    }
}

__device__ void matmul_sq(const float* A, const float* B, float* C, int d) {
    for (int i = 0; i < d; i++)
        for (int j = 0; j < d; j++) {
            float s = 0.0f;
            for (int k = 0; k < d; k++) s = fmaf(A[i * d + k], B[k * d + j], s);
            C[i * d + j] = s;
        }
}

__global__ void setup_kernel(const float* __restrict__ q,
                             const float* __restrict__ J1,
                             const float* __restrict__ J2,
                             int T) {
    int t = threadIdx.x;
    if (t >= T) return;

    float r = q[4 * t + 0], i = q[4 * t + 1], j = q[4 * t + 2], k = q[4 * t + 3];
    float inv = rsqrtf(r * r + i * i + j * j + k * k);
    r *= inv; i *= inv; j *= inv; k *= inv;
    float two_s = 2.0f / (r * r + i * i + j * j + k * k);

    float M01 = two_s * (i * j - k * r);
    float M21 = two_s * (j * k + i * r);
    float M11 = 1.0f - two_s * (i * i + k * k);
    float M10 = two_s * (i * j + k * r);
    float M12 = two_s * (j * k - i * r);

    float alpha = atan2f(M01, M21);
    float beta  = acosf(fmaxf(-1.0f, fminf(1.0f, M11)));
    float gamma = atan2f(M10, -M12);

    {
        float Za[9], Zb[9], Zg[9], t1[9], t2[9];
        zrot(alpha, 3, Za); zrot(beta, 3, Zb); zrot(gamma, 3, Zg);
        matmul_sq(Za, J1, t1, 3);
        matmul_sq(t1, Zb, t2, 3);
        matmul_sq(t2, J1, t1, 3);
        matmul_sq(t1, Zg, &g_D1[t * 9], 3);
    }
    {
        float Za[25], Zb[25], Zg[25], t1[25], t2[25];
        zrot(alpha, 5, Za); zrot(beta, 5, Zb); zrot(gamma, 5, Zg);
        matmul_sq(Za, J2, t1, 5);
        matmul_sq(t1, Zb, t2, 5);
        matmul_sq(t2, J2, t1, 5);
        matmul_sq(t1, Zg, &g_D2[t * 25], 5);
    }
}

// One block per point p. 128 threads (120 active). Each active thread owns one
// output float4 chunk (channels 4*tid .. 4*tid+3):
//   chunks  0..31  : l=0, direct copy from registers.
//   chunks 32..79  : l=1, each spans exactly 2 triples -> 6 input floats.
//   chunks 80..119 : l=2, spans <= 2 quintets -> <= 10 input floats.
// Inputs cached in registers (loaded once via smem). D matrices in smem
// (broadcast reads). Zero barriers inside the t-loop; one STG.128 per thread
// per t. This removes all staging traffic from the L1/LSU path.
__global__ __launch_bounds__(128) void transform_kernel(
        const float* __restrict__ feat,
        float* __restrict__ out,
        int N, int T) {
    __shared__ float sF[480];
    __shared__ float sD1[16 * 9];
    __shared__ float sD2[16 * 25];

    const int tid = threadIdx.x;
    const int p = blockIdx.x;

    for (int x = tid; x < 16 * 9; x += 128) sD1[x] = g_D1[x];
    for (int x = tid; x < 16 * 25; x += 128) sD2[x] = g_D2[x];

    const float* fr = feat + (size_t)p * 480;

    float4 f0;
    if (tid < 120) {
        f0 = reinterpret_cast<const float4*>(fr)[tid];
        reinterpret_cast<float4*>(sF)[tid] = f0;
    }
    __syncthreads();

    // Per-thread register setup (constant across t).
    float in6[6];                 // l=1 inputs
    float in10[10];               // l=2 inputs
    int a3[4], r3[4];             // l=1 per-element D row / input offset
    int a5[4], r5[4];             // l=2 per-element

    if (tid >= 32 && tid < 80) {
        const int j = tid - 32;
        const int off0 = 4 * j;
        const int m0 = off0 / 3;
#pragma unroll
        for (int b = 0; b < 6; b++) in6[b] = sF[128 + 3 * m0 + b];
#pragma unroll
        for (int e = 0; e < 4; e++) {
            int off = off0 + e;
            int m = off / 3;
            a3[e] = off - 3 * m;
            r3[e] = (m - m0) * 3;
        }
    } else if (tid >= 80 && tid < 120) {
        const int j = tid - 80;
        const int off0 = 4 * j;
        const int m0 = off0 / 5;
#pragma unroll
        for (int b = 0; b < 10; b++) {
            int idx = 320 + 5 * m0 + b;
            in10[b] = (idx < 480) ? sF[idx] : 0.0f;
        }
#pragma unroll
        for (int e = 0; e < 4; e++) {
            int off = off0 + e;
            int m = off / 5;
            a5[e] = off - 5 * m;
            r5[e] = (m - m0) * 5;
        }
    }

    if (tid >= 120) return;

    for (int t = 0; t < T; t++) {
        float* ob = out + ((size_t)t * N + p) * 480;
        float4 o;

        if (tid < 32) {
            o = f0;
        } else if (tid < 80) {
            const float* D = sD1 + t * 9;
            float v[4];
#pragma unroll
            for (int e = 0; e < 4; e++) {
                const float* Dr = D + 3 * a3[e];
                const float* in = in6 + r3[e];
                v[e] = fmaf(Dr[0], in[0], fmaf(Dr[1], in[1], Dr[2] * in[2]));
            }
            o = make_float4(v[0], v[1], v[2], v[3]);
        } else {
            const float* D = sD2 + t * 25;
            float v[4];
#pragma unroll
            for (int e = 0; e < 4; e++) {
                const float* Dr = D + 5 * a5[e];
                const float* in = in10 + r5[e];
                float s = Dr[0] * in[0];
                s = fmaf(Dr[1], in[1], s);
                s = fmaf(Dr[2], in[2], s);
                s = fmaf(Dr[3], in[3], s);
                s = fmaf(Dr[4], in[4], s);
                v[e] = s;
            }
            o = make_float4(v[0], v[1], v[2], v[3]);
        }

        reinterpret_cast<float4*>(ob)[tid] = o;
    }
}

extern "C" void kernel_launch(void* const* d_in, const int* in_sizes, int n_in,
                              void* d_out, int out_size) {
    const float* feat = (const float*)d_in[0];
    const float* q    = (const float*)d_in[1];
    // d_in[2] = J0 (unused: l=0 is a pure broadcast in the reference)
    const float* J1   = (const float*)d_in[3];
    const float* J2   = (const float*)d_in[4];
    float* out = (float*)d_out;

    const int T = in_sizes[1] / 4;     // 16
    const int N = in_sizes[0] / 480;   // 16384

    setup_kernel<<<1, 32>>>(q, J1, J2, T);
    transform_kernel<<<N, 128>>>(feat, out, N, T);
}

// round 5
// speedup vs baseline: 1.5628x; 1.5628x over previous
#include <cuda_runtime.h>
#include <cstdint>
#include <cstddef>

// Wigner D matrices per quaternion: D1 = 3x3 (l=1), D2 = 5x5 (l=2).
__device__ float g_D1[16 * 9];
__device__ float g_D2[16 * 25];

// Build z-rotation matrix of size d=2l+1.
// Reference order: sin on anti-diagonal first, then cos on diagonal (center -> cos).
__device__ void zrot(float ang, int d, float* M) {
    int l = (d - 1) / 2;
    for (int x = 0; x < d * d; x++) M[x] = 0.0f;
    for (int idx = 0; idx < d; idx++) {
        float fr = (float)(l - idx);
        M[idx * d + (d - 1 - idx)] = sinf(fr * ang);
        M[idx * d + idx]           = cosf(fr * ang);
    }
}

__device__ void matmul_sq(const float* A, const float* B, float* C, int d) {
    for (int i = 0; i < d; i++)
        for (int j = 0; j < d; j++) {
            float s = 0.0f;
            for (int k = 0; k < d; k++) s = fmaf(A[i * d + k], B[k * d + j], s);
            C[i * d + j] = s;
        }
}

__global__ void setup_kernel(const float* __restrict__ q,
                             const float* __restrict__ J1,
                             const float* __restrict__ J2,
                             int T) {
    int t = threadIdx.x;
    if (t >= T) return;

    float r = q[4 * t + 0], i = q[4 * t + 1], j = q[4 * t + 2], k = q[4 * t + 3];
    float inv = rsqrtf(r * r + i * i + j * j + k * k);
    r *= inv; i *= inv; j *= inv; k *= inv;
    float two_s = 2.0f / (r * r + i * i + j * j + k * k);

    float M01 = two_s * (i * j - k * r);
    float M21 = two_s * (j * k + i * r);
    float M11 = 1.0f - two_s * (i * i + k * k);
    float M10 = two_s * (i * j + k * r);
    float M12 = two_s * (j * k - i * r);

    float alpha = atan2f(M01, M21);
    float beta  = acosf(fmaxf(-1.0f, fminf(1.0f, M11)));
    float gamma = atan2f(M10, -M12);

    {
        float Za[9], Zb[9], Zg[9], t1[9], t2[9];
        zrot(alpha, 3, Za); zrot(beta, 3, Zb); zrot(gamma, 3, Zg);
        matmul_sq(Za, J1, t1, 3);
        matmul_sq(t1, Zb, t2, 3);
        matmul_sq(t2, J1, t1, 3);
        matmul_sq(t1, Zg, &g_D1[t * 9], 3);
    }
    {
        float Za[25], Zb[25], Zg[25], t1[25], t2[25];
        zrot(alpha, 5, Za); zrot(beta, 5, Zb); zrot(gamma, 5, Zg);
        matmul_sq(Za, J2, t1, 5);
        matmul_sq(t1, Zb, t2, 5);
        matmul_sq(t2, J2, t1, 5);
        matmul_sq(t1, Zg, &g_D2[t * 25], 5);
    }
}

// One block per 4 points. 128 threads:
//   tid 0..31  : l=0, hold 4 points' float4 chunks in regs, store directly.
//   tid 32..95 : l=1, thread owns m=tid-32, 4 points' triples in regs (static idx).
//   tid 96..127: l=2, thread owns m=tid-96, 4 points' quintets in regs.
// Per t: broadcast-read D rows from smem ONCE, reuse across 4 points (amortizes
// the dominant D-LDS wavefront cost 4x vs one-point blocks). Stage l1/l2
// outputs in double-buffered smem (stride 3/5 STS = conflict-free), one barrier
// per t, then coalesced float4 copy-out. All register indexing is
// compile-time (pp/b loops fully unrolled) -> no local-memory spills.
__global__ __launch_bounds__(128) void transform_kernel(
        const float* __restrict__ feat,
        float* __restrict__ out,
        int N, int T) {
    __shared__ float sStage[2][1408];   // 4 points x 352 staged channels, x2 buffers
    __shared__ float sD1[144];
    __shared__ float sD2[400];

    const int tid = threadIdx.x;
    const int pbase = blockIdx.x * 4;

    for (int x = tid; x < 144; x += 128) sD1[x] = g_D1[x];
    for (int x = tid; x < 400; x += 128) sD2[x] = g_D2[x];

    // Coalesced load of 4 points' features into smem (aliases the stage
    // buffers: 1920 floats needed <= 2816 available; barrier below separates).
    float* sF = &sStage[0][0];
    {
        const float4* src = reinterpret_cast<const float4*>(feat + (size_t)pbase * 480);
        float4* dst = reinterpret_cast<float4*>(sF);
        for (int x = tid; x < 480; x += 128) dst[x] = src[x];
    }
    __syncthreads();

    // Register gather (all indices compile-time after unrolling).
    float4 f0[4];
    float in1[4][3];
    float in2[4][5];
    if (tid < 32) {
#pragma unroll
        for (int pp = 0; pp < 4; pp++)
            f0[pp] = reinterpret_cast<const float4*>(sF + pp * 480)[tid];
    } else if (tid < 96) {
        const int m = tid - 32;
#pragma unroll
        for (int pp = 0; pp < 4; pp++)
#pragma unroll
            for (int b = 0; b < 3; b++)
                in1[pp][b] = sF[pp * 480 + 128 + 3 * m + b];
    } else {
        const int m = tid - 96;
#pragma unroll
        for (int pp = 0; pp < 4; pp++)
#pragma unroll
            for (int b = 0; b < 5; b++)
                in2[pp][b] = sF[pp * 480 + 320 + 5 * m + b];
    }
    __syncthreads();   // done reading sF before first stage write

    for (int t = 0; t < T; t++) {
        float* buf = sStage[t & 1];

        if (tid >= 32 && tid < 96) {
            const int m = tid - 32;
            const float* D = sD1 + t * 9;
#pragma unroll
            for (int a = 0; a < 3; a++) {
                const float d0 = D[a * 3 + 0];
                const float d1 = D[a * 3 + 1];
                const float d2 = D[a * 3 + 2];
#pragma unroll
                for (int pp = 0; pp < 4; pp++)
                    buf[pp * 352 + 3 * m + a] =
                        fmaf(d0, in1[pp][0], fmaf(d1, in1[pp][1], d2 * in1[pp][2]));
            }
        } else if (tid >= 96) {
            const int m = tid - 96;
            const float* D = sD2 + t * 25;
#pragma unroll
            for (int a = 0; a < 5; a++) {
                const float d0 = D[a * 5 + 0];
                const float d1 = D[a * 5 + 1];
                const float d2 = D[a * 5 + 2];
                const float d3 = D[a * 5 + 3];
                const float d4 = D[a * 5 + 4];
#pragma unroll
                for (int pp = 0; pp < 4; pp++) {
                    float s = d0 * in2[pp][0];
                    s = fmaf(d1, in2[pp][1], s);
                    s = fmaf(d2, in2[pp][2], s);
                    s = fmaf(d3, in2[pp][3], s);
                    s = fmaf(d4, in2[pp][4], s);
                    buf[pp * 352 + 192 + 5 * m + a] = s;
                }
            }
        }
        __syncthreads();
        // Single barrier per t is safe with double buffering: a thread reaches
        // the stage-write of iter t+2 (same buffer as t) only after passing the
        // barrier of iter t+1, which requires ALL threads to have finished
        // their iter-t copy-out.

        float* obase = out + ((size_t)t * N + pbase) * 480;
        if (tid < 32) {
#pragma unroll
            for (int pp = 0; pp < 4; pp++)
                reinterpret_cast<float4*>(obase + pp * 480)[tid] = f0[pp];
        } else {
            // 352 staged float4 chunks distributed over 96 threads.
            for (int x = tid - 32; x < 352; x += 96) {
                const int pp = x / 88;
                const int c4 = x - pp * 88;
                float4 v = reinterpret_cast<const float4*>(buf + pp * 352)[c4];
                reinterpret_cast<float4*>(obase + pp * 480 + 128)[c4] = v;
            }
        }
    }
}

extern "C" void kernel_launch(void* const* d_in, const int* in_sizes, int n_in,
                              void* d_out, int out_size) {
    const float* feat = (const float*)d_in[0];
    const float* q    = (const float*)d_in[1];
    // d_in[2] = J0 (unused: l=0 is a pure broadcast in the reference)
    const float* J1   = (const float*)d_in[3];
    const float* J2   = (const float*)d_in[4];
    float* out = (float*)d_out;

    const int T = in_sizes[1] / 4;     // 16
    const int N = in_sizes[0] / 480;   // 16384

    setup_kernel<<<1, 32>>>(q, J1, J2, T);
    transform_kernel<<<N / 4, 128>>>(feat, out, N, T);
}